// round 1
// baseline (speedup 1.0000x reference)
#include <cuda_runtime.h>

// Problem constants
#define Bc 32
#define Sc 128
#define Hc 128
#define BSH (Bc * Sc * Hc)

// Scratch (no cudaMalloc allowed)
__device__ float g_M[BSH];
__device__ float g_T[BSH];

// ---------------------------------------------------------------------------
// helpers
// ---------------------------------------------------------------------------
__device__ __forceinline__ float gelu_f(float x) {
    // exact GELU: 0.5*x*(1+erf(x/sqrt(2)))  (matches jax.nn.gelu approximate=False)
    return 0.5f * x * (1.0f + erff(x * 0.7071067811865476f));
}

__device__ __forceinline__ unsigned long long dup2(float x) {
    unsigned long long r;
    unsigned int u = __float_as_uint(x);
    asm("mov.b64 %0, {%1, %1};" : "=l"(r) : "r"(u));
    return r;
}

__device__ __forceinline__ void fma2(unsigned long long &d,
                                     unsigned long long a,
                                     unsigned long long b) {
    // packed 2x fp32 FMA (FFMA2) — 2x the fma-pipe throughput of scalar FFMA
    asm("fma.rn.f32x2 %0, %1, %2, %3;" : "=l"(d) : "l"(a), "l"(b), "l"(d));
}

__device__ __forceinline__ float lo32(unsigned long long v) {
    return __uint_as_float((unsigned int)v);
}
__device__ __forceinline__ float hi32(unsigned long long v) {
    return __uint_as_float((unsigned int)(v >> 32));
}

// ---------------------------------------------------------------------------
// Mix kernel: one block per (b, j).
//   Y[h,t] = sum_s X[b,s,h] * W1[j,s,t]          (128x128x(j+1) GEMM, ragged)
//   res[h] = sum_t gelu(Y[h,t] + b1[j,t]) * W2[j,t]
//   out[b,j,h] = base[b,j,h] + res[h] + b2[j]
// W1/b1/W2 are zero for s>j or t>j, so K-loop truncation at j+1 (tile-rounded)
// and skipping warps whose t-range is entirely > j are exact.
// ---------------------------------------------------------------------------
__global__ __launch_bounds__(256) void mix_kernel(
    const float* __restrict__ X,     // [B,S,H]
    const float* __restrict__ W1,    // [S,S,S] (this scale)
    const float* __restrict__ b1,    // [S,S]
    const float* __restrict__ W2,    // [S,S]
    const float* __restrict__ b2,    // [S]
    const float* __restrict__ base,  // [B,S,H]
    float* __restrict__ out)         // [B,S,H]
{
    __shared__ __align__(16) float Xs[16][Hc];       // Xs[kk][h]
    __shared__ __align__(16) float Ws[16][Sc];       // Ws[kk][t]
    __shared__ __align__(16) float red[16][Hc + 1];  // cross-tx reduction

    const int b  = blockIdx.x % Bc;
    const int j  = blockIdx.x / Bc;
    const int Jp = j + 1;

    const int tid = threadIdx.x;
    const int tx  = tid >> 4;   // 0..15 ; warp w covers tx {2w, 2w+1}
    const int ty  = tid & 15;   // 0..15
    const int t0  = tx * 8;
    const int h0  = ty * 8;
    const int w   = tid >> 5;
    const bool wact = (w * 16) < Jp;   // warp's t-range intersects the prefix

    const float* Xg  = X  + (long)b * Sc * Hc;  // X[b, s, h]
    const float* W1g = W1 + (long)j * Sc * Sc;  // W1[j, s, t]

    unsigned long long acc[8][4];
#pragma unroll
    for (int r = 0; r < 8; ++r)
#pragma unroll
        for (int c = 0; c < 4; ++c) acc[r][c] = 0ull;

    for (int k0 = 0; k0 < Jp; k0 += 16) {
        __syncthreads();
        // cooperative load: 16 rows x 128 floats each = 512 float4 per array
        {
            int idx = tid;
#pragma unroll
            for (int rp = 0; rp < 2; ++rp, idx += 256) {
                int row  = idx >> 5;
                int col4 = (idx & 31) * 4;
                *(float4*)&Xs[row][col4] =
                    *(const float4*)&Xg[(k0 + row) * Hc + col4];
                *(float4*)&Ws[row][col4] =
                    *(const float4*)&W1g[(k0 + row) * Sc + col4];
            }
        }
        __syncthreads();

        if (wact) {
#pragma unroll
            for (int kk = 0; kk < 16; ++kk) {
                float4 a0 = *(const float4*)&Xs[kk][h0];
                float4 a1 = *(const float4*)&Xs[kk][h0 + 4];
                ulonglong2 bv0 = *(const ulonglong2*)&Ws[kk][t0];
                ulonglong2 bv1 = *(const ulonglong2*)&Ws[kk][t0 + 4];
                unsigned long long bb0 = bv0.x, bb1 = bv0.y;
                unsigned long long bb2 = bv1.x, bb3 = bv1.y;
                float av[8] = {a0.x, a0.y, a0.z, a0.w, a1.x, a1.y, a1.z, a1.w};
#pragma unroll
                for (int r = 0; r < 8; ++r) {
                    unsigned long long ad = dup2(av[r]);
                    fma2(acc[r][0], ad, bb0);
                    fma2(acc[r][1], ad, bb1);
                    fma2(acc[r][2], ad, bb2);
                    fma2(acc[r][3], ad, bb3);
                }
            }
        }
    }

    // Epilogue: partial row-reductions over this thread's 8 t-columns
    float part[8];
#pragma unroll
    for (int r = 0; r < 8; ++r) part[r] = 0.0f;

    if (wact) {
#pragma unroll
        for (int c = 0; c < 8; ++c) {
            int t = t0 + c;
            float w2v = W2[j * Sc + t];   // zero for t > j
            float b1v = b1[j * Sc + t];   // zero for t > j
#pragma unroll
            for (int r = 0; r < 8; ++r) {
                unsigned long long v = acc[r][c >> 1];
                float y = ((c & 1) ? hi32(v) : lo32(v)) + b1v;
                part[r] += gelu_f(y) * w2v;
            }
        }
    }

#pragma unroll
    for (int r = 0; r < 8; ++r) red[tx][h0 + r] = part[r];
    __syncthreads();

    if (tid < Hc) {
        int h = tid;
        float s = base[((long)b * Sc + j) * Hc + h] + b2[j];
#pragma unroll
        for (int q = 0; q < 16; ++q) s += red[q][h];
        out[((long)b * Sc + j) * Hc + h] = s;
    }
}

// ---------------------------------------------------------------------------
// MLP GEMM: out[r,c] = act( sum_k in[r,k] * W[k,c] + bias[c] )
// rows tiled 32 per block (128 blocks for 4096 rows), full N=128.
// Thread: 2 rows x 8 cols, FFMA2 over column pairs.
// ---------------------------------------------------------------------------
__global__ __launch_bounds__(256) void mlp_kernel(
    const float* __restrict__ in,    // [4096,128]
    const float* __restrict__ W,     // [128,128] (in,out)
    const float* __restrict__ bias,  // [128]
    float* __restrict__ out,         // [4096,128]
    int act)
{
    __shared__ __align__(16) float Ins[16][33];   // transposed: Ins[kk][r]
    __shared__ __align__(16) float Ws[16][128];   // Ws[kk][c]

    const int tid = threadIdx.x;
    const int cx  = tid & 15;
    const int ry  = tid >> 4;
    const int c0  = cx * 8;
    const int r0g = blockIdx.x * 32;

    unsigned long long acc[2][4];
#pragma unroll
    for (int r = 0; r < 2; ++r)
#pragma unroll
        for (int c = 0; c < 4; ++c) acc[r][c] = 0ull;

    for (int k0 = 0; k0 < 128; k0 += 16) {
        __syncthreads();
        if (tid < 128) {
            int row = tid >> 2;
            int q4  = (tid & 3) * 4;
            float4 v = *(const float4*)&in[(r0g + row) * 128 + k0 + q4];
            Ins[q4 + 0][row] = v.x;
            Ins[q4 + 1][row] = v.y;
            Ins[q4 + 2][row] = v.z;
            Ins[q4 + 3][row] = v.w;
        }
        {
            int i = tid;
#pragma unroll
            for (int rp = 0; rp < 2; ++rp, i += 256) {
                int row = i >> 5;
                int c4  = (i & 31) * 4;
                *(float4*)&Ws[row][c4] = *(const float4*)&W[(k0 + row) * 128 + c4];
            }
        }
        __syncthreads();

#pragma unroll
        for (int kk = 0; kk < 16; ++kk) {
            float a0 = Ins[kk][ry * 2];
            float a1 = Ins[kk][ry * 2 + 1];
            ulonglong2 bv0 = *(const ulonglong2*)&Ws[kk][c0];
            ulonglong2 bv1 = *(const ulonglong2*)&Ws[kk][c0 + 4];
            unsigned long long ad0 = dup2(a0);
            unsigned long long ad1 = dup2(a1);
            fma2(acc[0][0], ad0, bv0.x);
            fma2(acc[0][1], ad0, bv0.y);
            fma2(acc[0][2], ad0, bv1.x);
            fma2(acc[0][3], ad0, bv1.y);
            fma2(acc[1][0], ad1, bv0.x);
            fma2(acc[1][1], ad1, bv0.y);
            fma2(acc[1][2], ad1, bv1.x);
            fma2(acc[1][3], ad1, bv1.y);
        }
    }

#pragma unroll
    for (int r = 0; r < 2; ++r) {
        int row = r0g + ry * 2 + r;
        float o[8];
#pragma unroll
        for (int c = 0; c < 8; ++c) {
            unsigned long long v = acc[r][c >> 1];
            float y = (c & 1) ? hi32(v) : lo32(v);
            y += bias[c0 + c];
            if (act) y = gelu_f(y);
            o[c] = y;
        }
        *(float4*)&out[row * 128 + c0]     = make_float4(o[0], o[1], o[2], o[3]);
        *(float4*)&out[row * 128 + c0 + 4] = make_float4(o[4], o[5], o[6], o[7]);
    }
}

// ---------------------------------------------------------------------------
__global__ void copy_kernel(const float4* __restrict__ src,
                            float4* __restrict__ dst, int n4)
{
    int i = blockIdx.x * blockDim.x + threadIdx.x;
    if (i < n4) dst[i] = src[i];
}

// ---------------------------------------------------------------------------
extern "C" void kernel_launch(void* const* d_in, const int* in_sizes, int n_in,
                              void* d_out, int out_size)
{
    const float* trend0 = (const float*)d_in[0];
    const float* trend1 = (const float*)d_in[1];
    const float* trend2 = (const float*)d_in[2];
    const float* W1     = (const float*)d_in[3];
    const float* b1     = (const float*)d_in[4];
    const float* W2     = (const float*)d_in[5];
    const float* b2     = (const float*)d_in[6];
    const float* Wm1    = (const float*)d_in[7];
    const float* bm1    = (const float*)d_in[8];
    const float* Wm2    = (const float*)d_in[9];
    const float* bm2    = (const float*)d_in[10];

    float* out = (float*)d_out;
    float* O0 = out;             // mlp(trend0 + res1)
    float* O1 = out + BSH;       // mlp(trend1 + res0)
    float* O2 = out + 2 * BSH;   // trend2

    float *pM, *pT;
    cudaGetSymbolAddress((void**)&pM, g_M);
    cudaGetSymbolAddress((void**)&pT, g_T);

    dim3 blk(256);
    dim3 mixGrid(Bc * Sc);          // 4096 blocks, b fastest (W1[j] L2 reuse)
    dim3 mlpGrid(Bc * Sc / 32);     // 128 blocks

    // scale i=0: X = trend2, base = trend1 -> O1 = mlp(M0)
    mix_kernel<<<mixGrid, blk>>>(trend2, W1, b1, W2, b2, trend1, pM);
    mlp_kernel<<<mlpGrid, blk>>>(pM, Wm1, bm1, pT, 1);
    mlp_kernel<<<mlpGrid, blk>>>(pT, Wm2, bm2, O1, 0);

    // scale i=1: X = O1, base = trend0 -> O0 = mlp(M1)
    mix_kernel<<<mixGrid, blk>>>(O1, W1 + Sc * Sc * Sc, b1 + Sc * Sc,
                                 W2 + Sc * Sc, b2 + Sc, trend0, pM);
    mlp_kernel<<<mlpGrid, blk>>>(pM, Wm1, bm1, pT, 1);
    mlp_kernel<<<mlpGrid, blk>>>(pT, Wm2, bm2, O0, 0);

    // out2 = trend2
    copy_kernel<<<BSH / 4 / 256, 256>>>((const float4*)trend2, (float4*)O2,
                                        BSH / 4);
}